// round 3
// baseline (speedup 1.0000x reference)
#include <cuda_runtime.h>

// Chamfer distance, B=2, N=8192, 3D points.
// Per direction minimize h_j = 0.5*||p_j||^2 - q_i . p_j, sqrt after the min.
// Inner loop: packed fma.rn.f32x2 (FFMA2), 2 reference points per instruction.
// Per 2 pairs: 3 FFMA2 (fma pipe) + 2 FMNMX (alu pipe); LDS amortized over ITILE=8.

#define BATCH   2
#define NPTS    8192
#define THREADS 128
#define ITILE   8
#define QBLK    (THREADS * ITILE)   // 1024 queries per CTA
#define NQBLK   (NPTS / QBLK)       // 8
#define JCHUNKS 64
#define JCHUNK  (NPTS / JCHUNKS)    // 128 refs per chunk
#define JPAIRS  (JCHUNK / 2)        // 64

// Scratch: partial min squared distance per (dir*B+b, chunk, query). 8.4 MB (L2-resident).
__device__ float g_partial[2 * BATCH * JCHUNKS * NPTS];
__device__ float g_blocksum[64];

typedef unsigned long long u64;

__device__ __forceinline__ u64 pack2(float lo, float hi) {
    u64 d; asm("mov.b64 %0, {%1,%2};" : "=l"(d) : "f"(lo), "f"(hi)); return d;
}
__device__ __forceinline__ void unpack2(u64 d, float& lo, float& hi) {
    asm("mov.b64 {%0,%1}, %2;" : "=f"(lo), "=f"(hi) : "l"(d));
}
__device__ __forceinline__ u64 fma2(u64 a, u64 b, u64 c) {
    u64 d; asm("fma.rn.f32x2 %0, %1, %2, %3;" : "=l"(d) : "l"(a), "l"(b), "l"(c));
    return d;
}

__global__ __launch_bounds__(THREADS, 6)
void chamfer_pass(const float* __restrict__ pred, const float* __restrict__ gt) {
    const int chunk  = blockIdx.x;          // 0..JCHUNKS-1
    const int qblock = blockIdx.y;          // 0..NQBLK-1
    const int bz     = blockIdx.z;          // dir*BATCH + b, 0..3
    const int dir    = bz >> 1;
    const int b      = bz & 1;

    // dir 0: queries = gt, refs = pred; dir 1: queries = pred, refs = gt
    const float* __restrict__ qarr = dir ? pred : gt;
    const float* __restrict__ rarr = dir ? gt   : pred;

    // Pair-packed reference staging: sxy[jp] = {x0,x1,y0,y1}, szc[jp] = {z0,z1,c0,c1}
    __shared__ float4 sxy[JPAIRS];
    __shared__ float4 szc[JPAIRS];

    const int jbase = chunk * JCHUNK;
    if (threadIdx.x < JPAIRS) {
        const int jp = threadIdx.x;
        const float* r = rarr + ((size_t)b * NPTS + jbase + 2 * jp) * 3;
        float x0 = r[0], y0 = r[1], z0 = r[2];
        float x1 = r[3], y1 = r[4], z1 = r[5];
        float c0 = 0.5f * (x0 * x0 + y0 * y0 + z0 * z0);
        float c1 = 0.5f * (x1 * x1 + y1 * y1 + z1 * z1);
        sxy[jp] = make_float4(x0, x1, y0, y1);
        szc[jp] = make_float4(z0, z1, c0, c1);
    }

    // Per-thread queries: negated coords replicated into both f32x2 halves.
    // (||q||^2 is recomputed at the end from these — saves 8 registers.)
    u64 nx2[ITILE], ny2[ITILE], nz2[ITILE];
    float mA[ITILE], mB[ITILE];
    const int q0 = qblock * QBLK + threadIdx.x;
#pragma unroll
    for (int k = 0; k < ITILE; k++) {
        const float* g = qarr + ((size_t)b * NPTS + q0 + k * THREADS) * 3;
        float x = g[0], y = g[1], z = g[2];
        nx2[k] = pack2(-x, -x);
        ny2[k] = pack2(-y, -y);
        nz2[k] = pack2(-z, -z);
        mA[k]  = 3.4e38f;
        mB[k]  = 3.4e38f;
    }
    __syncthreads();

    const ulonglong2* __restrict__ pxy = reinterpret_cast<const ulonglong2*>(sxy);
    const ulonglong2* __restrict__ pzc = reinterpret_cast<const ulonglong2*>(szc);

#pragma unroll 8
    for (int jp = 0; jp < JPAIRS; jp++) {
        ulonglong2 vxy = pxy[jp];   // {x0,x1},{y0,y1}  (LDS.128 broadcast)
        ulonglong2 vzc = pzc[jp];   // {z0,z1},{c0,c1}
#pragma unroll
        for (int k = 0; k < ITILE; k++) {
            u64 h2 = fma2(nz2[k], vzc.x, vzc.y);
            h2 = fma2(ny2[k], vxy.y, h2);
            h2 = fma2(nx2[k], vxy.x, h2);
            float h0, h1; unpack2(h2, h0, h1);   // register aliasing, no MOV
            mA[k] = fminf(mA[k], h0);
            mB[k] = fminf(mB[k], h1);
        }
    }

    float* out = g_partial + ((size_t)bz * JCHUNKS + chunk) * NPTS;
#pragma unroll
    for (int k = 0; k < ITILE; k++) {
        float x, xx; unpack2(nx2[k], x, xx);
        float y, yy; unpack2(ny2[k], y, yy);
        float z, zz; unpack2(nz2[k], z, zz);
        float qs = x * x + y * y + z * z;          // sign lost by squaring
        float m  = fminf(mA[k], mB[k]);
        float sq = fmaxf(fmaf(2.0f, m, qs), 0.0f); // clamp commutes with min
        out[q0 + k * THREADS] = sq;
    }
}

// Stage 1: min over chunks, sqrt, per-block sum. 64 blocks x 256 threads,
// 2 queries/thread covers 2*BATCH*NPTS = 32768 query slots.
__global__ __launch_bounds__(256)
void chamfer_reduce_a() {
    __shared__ float ssum[256];
    float acc = 0.0f;
#pragma unroll
    for (int r = 0; r < 2; r++) {
        int f  = blockIdx.x * 512 + r * 256 + threadIdx.x;  // 0..32767
        int db = f / NPTS;
        int q  = f % NPTS;
        const float* p = g_partial + (size_t)db * JCHUNKS * NPTS + q;
        float mv = 3.4e38f;
#pragma unroll 8
        for (int c = 0; c < JCHUNKS; c++) mv = fminf(mv, p[(size_t)c * NPTS]);
        acc += sqrtf(mv);
    }
    ssum[threadIdx.x] = acc;
    __syncthreads();
    for (int s = 128; s > 0; s >>= 1) {
        if (threadIdx.x < s) ssum[threadIdx.x] += ssum[threadIdx.x + s];
        __syncthreads();
    }
    if (threadIdx.x == 0) g_blocksum[blockIdx.x] = ssum[0];
}

// Stage 2: final deterministic sum of the 64 block sums.
__global__ void chamfer_reduce_b(float* __restrict__ out) {
    __shared__ float s[64];
    s[threadIdx.x] = g_blocksum[threadIdx.x];
    __syncthreads();
    for (int st = 32; st > 0; st >>= 1) {
        if (threadIdx.x < st) s[threadIdx.x] += s[threadIdx.x + st];
        __syncthreads();
    }
    if (threadIdx.x == 0) out[0] = s[0] / (float)(BATCH * NPTS);
}

extern "C" void kernel_launch(void* const* d_in, const int* in_sizes, int n_in,
                              void* d_out, int out_size) {
    const float* pred = (const float*)d_in[0];
    const float* gt   = (const float*)d_in[1];
    float* out        = (float*)d_out;

    dim3 grid(JCHUNKS, NQBLK, 2 * BATCH);   // 64 x 8 x 4 = 2048 CTAs
    chamfer_pass<<<grid, THREADS>>>(pred, gt);
    chamfer_reduce_a<<<64, 256>>>();
    chamfer_reduce_b<<<1, 64>>>(out);
}

// round 4
// speedup vs baseline: 1.0447x; 1.0447x over previous
#include <cuda_runtime.h>

// Chamfer distance, B=2, N=8192, 3D points.
// Per direction minimize h_j = 0.5*||p_j||^2 - q_i . p_j, sqrt after the min.
// Inner loop: packed fma.rn.f32x2 (FFMA2): per 2 refs = 3 FFMA2 + 2 FMNMX.
// Scheduling: 864 equal-work CTAs = 32 query-groups x 27 ref-splits -> one wave.

#define BATCH    2
#define NPTS     8192
#define THREADS  128
#define ITILE    8
#define QBLK     (THREADS * ITILE)   // 1024 queries per CTA
#define NQB      (NPTS / QBLK)       // 8
#define NGROUP   (4 * NQB)           // 32 (dir*batch x qblock)
#define CSPLIT   27                  // ref-range splits per group
#define NCTA     (NGROUP * CSPLIT)   // 864 <= 888 resident -> single wave
#define TOTPAIRS (NPTS / 2)          // 4096 ref pairs per (b,dir)
#define MAXPAIRS 152                 // ceil(4096/27)

// Per-CTA partial min sq-dist: [group*CSPLIT + c][qlocal]. 3.5 MB, L2-resident.
__device__ float g_partial[NCTA * QBLK];
__device__ float g_blocksum[128];

typedef unsigned long long u64;

__device__ __forceinline__ u64 pack2(float lo, float hi) {
    u64 d; asm("mov.b64 %0, {%1,%2};" : "=l"(d) : "f"(lo), "f"(hi)); return d;
}
__device__ __forceinline__ void unpack2(u64 d, float& lo, float& hi) {
    asm("mov.b64 {%0,%1}, %2;" : "=f"(lo), "=f"(hi) : "l"(d));
}
__device__ __forceinline__ u64 fma2(u64 a, u64 b, u64 c) {
    u64 d; asm("fma.rn.f32x2 %0, %1, %2, %3;" : "=l"(d) : "l"(a), "l"(b), "l"(c));
    return d;
}

__global__ __launch_bounds__(THREADS, 6)
void chamfer_pass(const float* __restrict__ pred, const float* __restrict__ gt) {
    const int bid    = blockIdx.x;
    const int g      = bid / CSPLIT;        // 0..31
    const int c      = bid - g * CSPLIT;    // 0..26
    const int bz     = g >> 3;              // dir*BATCH + b
    const int qblock = g & (NQB - 1);
    const int dir    = bz >> 1;
    const int b      = bz & 1;

    // dir 0: queries = gt, refs = pred; dir 1: queries = pred, refs = gt
    const float* __restrict__ qarr = dir ? pred : gt;
    const float* __restrict__ rarr = dir ? gt   : pred;

    // This CTA's contiguous ref-pair range (151 or 152 pairs).
    const int pstart = (c * TOTPAIRS) / CSPLIT;
    const int pend   = ((c + 1) * TOTPAIRS) / CSPLIT;
    const int npairs = pend - pstart;

    // Pair-packed staging: sxy = {x0,x1,y0,y1}, szc = {z0,z1,c0,c1}
    __shared__ float4 sxy[MAXPAIRS];
    __shared__ float4 szc[MAXPAIRS];

    for (int jp = threadIdx.x; jp < npairs; jp += THREADS) {
        const float* r = rarr + ((size_t)b * NPTS + 2 * (pstart + jp)) * 3;
        float x0 = r[0], y0 = r[1], z0 = r[2];
        float x1 = r[3], y1 = r[4], z1 = r[5];
        float c0 = 0.5f * (x0 * x0 + y0 * y0 + z0 * z0);
        float c1 = 0.5f * (x1 * x1 + y1 * y1 + z1 * z1);
        sxy[jp] = make_float4(x0, x1, y0, y1);
        szc[jp] = make_float4(z0, z1, c0, c1);
    }

    // Per-thread queries: negated coords replicated into both f32x2 halves.
    u64 nx2[ITILE], ny2[ITILE], nz2[ITILE];
    float mA[ITILE], mB[ITILE];
    const int q0 = qblock * QBLK + threadIdx.x;
#pragma unroll
    for (int k = 0; k < ITILE; k++) {
        const float* q = qarr + ((size_t)b * NPTS + q0 + k * THREADS) * 3;
        float x = q[0], y = q[1], z = q[2];
        nx2[k] = pack2(-x, -x);
        ny2[k] = pack2(-y, -y);
        nz2[k] = pack2(-z, -z);
        mA[k]  = 3.4e38f;
        mB[k]  = 3.4e38f;
    }
    __syncthreads();

    const ulonglong2* __restrict__ pxy = reinterpret_cast<const ulonglong2*>(sxy);
    const ulonglong2* __restrict__ pzc = reinterpret_cast<const ulonglong2*>(szc);

#pragma unroll 4
    for (int jp = 0; jp < npairs; jp++) {
        ulonglong2 vxy = pxy[jp];   // {x0,x1},{y0,y1}  (LDS.128 broadcast)
        ulonglong2 vzc = pzc[jp];   // {z0,z1},{c0,c1}
#pragma unroll
        for (int k = 0; k < ITILE; k++) {
            u64 h2 = fma2(nz2[k], vzc.x, vzc.y);
            h2 = fma2(ny2[k], vxy.y, h2);
            h2 = fma2(nx2[k], vxy.x, h2);
            float h0, h1; unpack2(h2, h0, h1);   // register aliasing, no MOV
            mA[k] = fminf(mA[k], h0);
            mB[k] = fminf(mB[k], h1);
        }
    }

    // Coalesced partial write: [bid][qlocal]
    float* out = g_partial + (size_t)bid * QBLK;
#pragma unroll
    for (int k = 0; k < ITILE; k++) {
        float x, xd; unpack2(nx2[k], x, xd);
        float y, yd; unpack2(ny2[k], y, yd);
        float z, zd; unpack2(nz2[k], z, zd);
        float qs = x * x + y * y + z * z;           // sign lost by squaring
        float m  = fminf(mA[k], mB[k]);
        float sq = fmaxf(fmaf(2.0f, m, qs), 0.0f);  // clamp commutes with min
        out[threadIdx.x + k * THREADS] = sq;
    }
}

// Stage 1: per-query min over the 27 ref-splits (coalesced), sqrt, block sum.
// 128 blocks x 256 threads = 32768 threads = one per query slot.
__global__ __launch_bounds__(256)
void chamfer_reduce_a() {
    __shared__ float ssum[256];
    const int qid    = blockIdx.x * 256 + threadIdx.x;  // 0..32767
    const int gq     = qid >> 10;        // group (block-uniform: 256 | 1024)
    const int qlocal = qid & (QBLK - 1);
    const float* p = g_partial + ((size_t)gq * CSPLIT) * QBLK + qlocal;
    float mv = 3.4e38f;
#pragma unroll
    for (int cc = 0; cc < CSPLIT; cc++) mv = fminf(mv, p[(size_t)cc * QBLK]);
    ssum[threadIdx.x] = sqrtf(mv);
    __syncthreads();
    for (int s = 128; s > 0; s >>= 1) {
        if (threadIdx.x < s) ssum[threadIdx.x] += ssum[threadIdx.x + s];
        __syncthreads();
    }
    if (threadIdx.x == 0) g_blocksum[blockIdx.x] = ssum[0];
}

// Stage 2: final deterministic sum of 128 block sums.
__global__ void chamfer_reduce_b(float* __restrict__ out) {
    __shared__ float s[128];
    s[threadIdx.x] = g_blocksum[threadIdx.x];
    __syncthreads();
    for (int st = 64; st > 0; st >>= 1) {
        if (threadIdx.x < st) s[threadIdx.x] += s[threadIdx.x + st];
        __syncthreads();
    }
    if (threadIdx.x == 0) out[0] = s[0] / (float)(BATCH * NPTS);
}

extern "C" void kernel_launch(void* const* d_in, const int* in_sizes, int n_in,
                              void* d_out, int out_size) {
    const float* pred = (const float*)d_in[0];
    const float* gt   = (const float*)d_in[1];
    float* out        = (float*)d_out;

    chamfer_pass<<<NCTA, THREADS>>>(pred, gt);
    chamfer_reduce_a<<<128, 256>>>();
    chamfer_reduce_b<<<1, 128>>>(out);
}